// round 1
// baseline (speedup 1.0000x reference)
#include <cuda_runtime.h>
#include <cstddef>

#define B_ 8
#define C_ 1024
#define Q_ 128
#define E_ 512
#define H_ 1024
#define FE (4 * E_)   // 2048

// ------------------------- scratch (static device globals) -------------------------
__device__ float g_qw[B_ * Q_];
__device__ float g_cw[B_ * C_];
__device__ float g_qmT[B_ * E_ * Q_];            // (b, e, q): question*w_multiple, transposed
__device__ float g_sim[B_ * C_ * Q_];            // sim, then softmax probs in place
__device__ float g_rowmax[B_ * C_];
__device__ float g_c2q[B_ * C_ * E_];
__device__ float g_q2c[B_ * E_];
__device__ float g_att[(size_t)B_ * C_ * FE];    // 64 MB
__device__ float g_h[(size_t)B_ * C_ * H_];      // 32 MB

// ------------------------- row . w dot products -------------------------
__global__ void dot_w_kernel(const float* __restrict__ X, const float* __restrict__ w,
                             float* __restrict__ out, int E) {
    int row = blockIdx.x;
    const float* x = X + (size_t)row * E;
    float s = 0.f;
    for (int e = threadIdx.x; e < E; e += blockDim.x) s += x[e] * w[e];
    __shared__ float red[32];
    #pragma unroll
    for (int o = 16; o > 0; o >>= 1) s += __shfl_down_sync(0xffffffffu, s, o);
    if ((threadIdx.x & 31) == 0) red[threadIdx.x >> 5] = s;
    __syncthreads();
    if (threadIdx.x < 32) {
        float v = (threadIdx.x < (blockDim.x >> 5)) ? red[threadIdx.x] : 0.f;
        #pragma unroll
        for (int o = 16; o > 0; o >>= 1) v += __shfl_down_sync(0xffffffffu, v, o);
        if (threadIdx.x == 0) out[row] = v;
    }
}

// ------------------------- qmT[b][e][q] = question[b][q][e] * w_mult[e] -------------------------
__global__ void build_qmT_kernel(const float* __restrict__ question,
                                 const float* __restrict__ w_mult) {
    int idx = blockIdx.x * blockDim.x + threadIdx.x;
    if (idx >= B_ * E_ * Q_) return;
    int q = idx % Q_;
    int e = (idx / Q_) % E_;
    int b = idx / (Q_ * E_);
    g_qmT[idx] = question[((size_t)b * Q_ + q) * E_ + e] * w_mult[e];
}

// ------------------------- generic 128x128 SGEMM, batched via blockIdx.z -------------------------
// C[bz] = A[bz](MxK, row-major) @ B[bz](KxN, row-major)
// epilogue: + rowAdd[bz*sRow + row] + colAdd[bz*sCol + col], * rowMul[row], relu
__global__ __launch_bounds__(256) void sgemm128_kernel(
    const float* __restrict__ A, const float* __restrict__ Bm, float* __restrict__ C,
    int M, int N, int K,
    size_t sA, size_t sB, size_t sC,
    const float* __restrict__ rowAdd, int sRow,
    const float* __restrict__ colAdd, int sCol,
    const float* __restrict__ rowMul,
    int relu) {
    const int BM = 128, BN = 128, BK = 16, TM = 8, TN = 8;
    __shared__ float As[BK][BM];
    __shared__ float Bs[BK][BN];
    int bz = blockIdx.z;
    A += bz * sA; Bm += bz * sB; C += bz * sC;
    int block_row = blockIdx.y * BM;
    int block_col = blockIdx.x * BN;
    int tid = threadIdx.x;
    int tx = tid & 15, ty = tid >> 4;
    float acc[TM][TN];
    #pragma unroll
    for (int i = 0; i < TM; i++)
        #pragma unroll
        for (int j = 0; j < TN; j++) acc[i][j] = 0.f;

    for (int k0 = 0; k0 < K; k0 += BK) {
        #pragma unroll
        for (int i = 0; i < 8; i++) {           // A tile: 128x16 = 2048 = 8 per thread
            int idx = tid + i * 256;
            int m = idx >> 4, k = idx & 15;
            As[k][m] = A[(size_t)(block_row + m) * K + k0 + k];
        }
        #pragma unroll
        for (int i = 0; i < 8; i++) {           // B tile: 16x128
            int idx = tid + i * 256;
            int k = idx >> 7, n = idx & 127;
            Bs[k][n] = Bm[(size_t)(k0 + k) * N + block_col + n];
        }
        __syncthreads();
        #pragma unroll
        for (int k = 0; k < BK; k++) {
            float a[TM], bf[TN];
            #pragma unroll
            for (int i = 0; i < TM; i++) a[i] = As[k][ty * TM + i];
            #pragma unroll
            for (int j = 0; j < TN; j++) bf[j] = Bs[k][tx * TN + j];
            #pragma unroll
            for (int i = 0; i < TM; i++)
                #pragma unroll
                for (int j = 0; j < TN; j++) acc[i][j] += a[i] * bf[j];
        }
        __syncthreads();
    }

    #pragma unroll
    for (int i = 0; i < TM; i++) {
        int row = block_row + ty * TM + i;
        float radd = rowAdd ? rowAdd[bz * sRow + row] : 0.f;
        float rmul = rowMul ? rowMul[row] : 1.f;
        #pragma unroll
        for (int j = 0; j < TN; j++) {
            int col = block_col + tx * TN + j;
            float v = acc[i][j] + radd + (colAdd ? colAdd[bz * sCol + col] : 0.f);
            v *= rmul;
            if (relu) v = fmaxf(v, 0.f);
            C[(size_t)row * N + col] = v;
        }
    }
}

// ------------------------- per-row softmax over q, keep rowmax -------------------------
__global__ void softmax_q_kernel() {
    int row = blockIdx.x;                 // b*C + c
    float* s = g_sim + (size_t)row * Q_;
    int t = threadIdx.x;                  // 128 threads
    float v = s[t];
    __shared__ float sh[Q_];
    sh[t] = v; __syncthreads();
    #pragma unroll
    for (int o = 64; o > 0; o >>= 1) { if (t < o) sh[t] = fmaxf(sh[t], sh[t + o]); __syncthreads(); }
    float m = sh[0]; __syncthreads();
    if (t == 0) g_rowmax[row] = m;
    float e = expf(v - m);
    sh[t] = e; __syncthreads();
    #pragma unroll
    for (int o = 64; o > 0; o >>= 1) { if (t < o) sh[t] += sh[t + o]; __syncthreads(); }
    float sum = sh[0];
    s[t] = e / sum;
}

// ------------------------- q2c: softmax over c of rowmax, then weighted sum of context -------------------------
__global__ void q2c_kernel(const float* __restrict__ context) {
    int b = blockIdx.x;
    __shared__ float w[C_];
    __shared__ float red[256];
    int t = threadIdx.x;                  // 256 threads
    const float* rm = g_rowmax + b * C_;
    float mx = -1e30f;
    for (int c = t; c < C_; c += 256) mx = fmaxf(mx, rm[c]);
    red[t] = mx; __syncthreads();
    #pragma unroll
    for (int o = 128; o > 0; o >>= 1) { if (t < o) red[t] = fmaxf(red[t], red[t + o]); __syncthreads(); }
    mx = red[0]; __syncthreads();
    float sum = 0.f;
    for (int c = t; c < C_; c += 256) { float e = expf(rm[c] - mx); w[c] = e; sum += e; }
    red[t] = sum; __syncthreads();
    #pragma unroll
    for (int o = 128; o > 0; o >>= 1) { if (t < o) red[t] += red[t + o]; __syncthreads(); }
    float inv = 1.f / red[0]; __syncthreads();
    const float* ctx = context + (size_t)b * C_ * E_;
    for (int e0 = t; e0 < E_; e0 += 256) {
        float acc = 0.f;
        #pragma unroll 4
        for (int c = 0; c < C_; c++) acc += w[c] * ctx[(size_t)c * E_ + e0];
        g_q2c[b * E_ + e0] = acc * inv;
    }
}

// ------------------------- attended = [ctx, c2q, ctx*c2q, ctx*q2c] -------------------------
__global__ void build_attended_kernel(const float* __restrict__ context) {
    size_t idx = (size_t)blockIdx.x * blockDim.x + threadIdx.x;   // over B*C*E
    if (idx >= (size_t)B_ * C_ * E_) return;
    int e = idx % E_;
    size_t bc = idx / E_;
    int b = (int)(bc / C_);
    float ctx = context[idx];
    float cq = g_c2q[idx];
    float qc = g_q2c[b * E_ + e];
    float* row = g_att + bc * FE;
    row[e] = ctx;
    row[E_ + e] = cq;
    row[2 * E_ + e] = ctx * cq;
    row[3 * E_ + e] = ctx * qc;
}

// ------------------------- launch -------------------------
extern "C" void kernel_launch(void* const* d_in, const int* in_sizes, int n_in,
                              void* d_out, int out_size) {
    const float* context   = (const float*)d_in[0];
    const float* question  = (const float*)d_in[1];
    const float* mask      = (const float*)d_in[2];
    const float* w_question= (const float*)d_in[3];
    const float* w_context = (const float*)d_in[4];
    const float* w_multiple= (const float*)d_in[5];
    const float* W1        = (const float*)d_in[6];
    const float* b1        = (const float*)d_in[7];
    const float* W2        = (const float*)d_in[8];
    const float* b2        = (const float*)d_in[9];
    float* out = (float*)d_out;

    float *p_qw, *p_cw, *p_qmT, *p_sim, *p_c2q, *p_h, *p_att;
    cudaGetSymbolAddress((void**)&p_qw,  g_qw);
    cudaGetSymbolAddress((void**)&p_cw,  g_cw);
    cudaGetSymbolAddress((void**)&p_qmT, g_qmT);
    cudaGetSymbolAddress((void**)&p_sim, g_sim);
    cudaGetSymbolAddress((void**)&p_c2q, g_c2q);
    cudaGetSymbolAddress((void**)&p_h,   g_h);
    cudaGetSymbolAddress((void**)&p_att, g_att);

    // 1-2: qw, cw
    dot_w_kernel<<<B_ * Q_, 128>>>(question, w_question, p_qw, E_);
    dot_w_kernel<<<B_ * C_, 128>>>(context, w_context, p_cw, E_);

    // 3: qmT
    build_qmT_kernel<<<(B_ * E_ * Q_ + 255) / 256, 256>>>(question, w_multiple);

    // 4: sim = context @ qmT  + cw[row] + qw[col]   (batched, M=1024 N=128 K=512)
    {
        dim3 grid(Q_ / 128, C_ / 128, B_);
        sgemm128_kernel<<<grid, 256>>>(context, p_qmT, p_sim,
                                       C_, Q_, E_,
                                       (size_t)C_ * E_, (size_t)E_ * Q_, (size_t)C_ * Q_,
                                       p_cw, C_, p_qw, Q_, nullptr, 0);
    }

    // 5: softmax over q (in place) + rowmax
    softmax_q_kernel<<<B_ * C_, Q_>>>();

    // 6: c2q = probs @ question   (batched, M=1024 N=512 K=128)
    {
        dim3 grid(E_ / 128, C_ / 128, B_);
        sgemm128_kernel<<<grid, 256>>>(p_sim, question, p_c2q,
                                       C_, E_, Q_,
                                       (size_t)C_ * Q_, (size_t)Q_ * E_, (size_t)C_ * E_,
                                       nullptr, 0, nullptr, 0, nullptr, 0);
    }

    // 7: q2c
    q2c_kernel<<<B_, 256>>>(context);

    // 8: attended concat
    build_attended_kernel<<<(B_ * C_ * E_ + 255) / 256, 256>>>(context);

    // 9: h = (attended @ W1 + b1) * mask    (M=8192 N=1024 K=2048)
    {
        dim3 grid(H_ / 128, (B_ * C_) / 128, 1);
        sgemm128_kernel<<<grid, 256>>>(p_att, W1, p_h,
                                       B_ * C_, H_, FE,
                                       0, 0, 0,
                                       nullptr, 0, b1, 0, mask, 0);
    }

    // 10: out = relu((h @ W2 + b2) * mask)  (M=8192 N=2048 K=1024)
    {
        dim3 grid(FE / 128, (B_ * C_) / 128, 1);
        sgemm128_kernel<<<grid, 256>>>(p_h, W2, out,
                                       B_ * C_, FE, H_,
                                       0, 0, 0,
                                       nullptr, 0, b2, 0, mask, 1);
    }
}

// round 4
// speedup vs baseline: 2.0306x; 2.0306x over previous
#include <cuda_runtime.h>
#include <cuda_bf16.h>
#include <cstdint>
#include <cstddef>

#define B_ 8
#define C_ 1024
#define Q_ 128
#define E_ 512
#define H_ 1024
#define FE (4 * E_)   // 2048

// ---------------- helpers ----------------
__device__ __forceinline__ uint32_t smem_u32(const void* p) {
    uint32_t a;
    asm("{ .reg .u64 t; cvta.to.shared.u64 t, %1; cvt.u32.u64 %0, t; }" : "=r"(a) : "l"(p));
    return a;
}
#define CP_ASYNC16(dst, src) \
    asm volatile("cp.async.cg.shared.global [%0], [%1], 16;" :: "r"(dst), "l"(src) : "memory")
#define CP_COMMIT() asm volatile("cp.async.commit_group;" ::: "memory")

// ---------------- scratch ----------------
__device__ float g_qw[B_ * Q_];
__device__ float g_cw[B_ * C_];
__device__ float g_qmT[B_ * E_ * Q_];
__device__ float g_sim[B_ * C_ * Q_];
__device__ float g_rowmax[B_ * C_];
__device__ float g_c2q[B_ * C_ * E_];
__device__ float g_q2c[B_ * E_];
// bf16 split operands:  A' = [hi | lo | hi],  B'^T = [hi | hi | lo]
__device__ __nv_bfloat16 g_A1[(size_t)B_ * C_ * 3 * FE];  // 8192 x 6144
__device__ __nv_bfloat16 g_B1[(size_t)H_ * 3 * FE];       // 1024 x 6144
__device__ __nv_bfloat16 g_A2[(size_t)B_ * C_ * 3 * H_];  // 8192 x 3072
__device__ __nv_bfloat16 g_B2[(size_t)FE * 3 * H_];       // 2048 x 3072

// ---------------- attention front-end (scalar, unchanged from passing R1) ----------------
__global__ void dot_w_kernel(const float* __restrict__ X, const float* __restrict__ w,
                             float* __restrict__ out, int E) {
    int row = blockIdx.x;
    const float* x = X + (size_t)row * E;
    float s = 0.f;
    for (int e = threadIdx.x; e < E; e += blockDim.x) s += x[e] * w[e];
    __shared__ float red[32];
    #pragma unroll
    for (int o = 16; o > 0; o >>= 1) s += __shfl_down_sync(0xffffffffu, s, o);
    if ((threadIdx.x & 31) == 0) red[threadIdx.x >> 5] = s;
    __syncthreads();
    if (threadIdx.x < 32) {
        float v = (threadIdx.x < (blockDim.x >> 5)) ? red[threadIdx.x] : 0.f;
        #pragma unroll
        for (int o = 16; o > 0; o >>= 1) v += __shfl_down_sync(0xffffffffu, v, o);
        if (threadIdx.x == 0) out[row] = v;
    }
}

__global__ void build_qmT_kernel(const float* __restrict__ question,
                                 const float* __restrict__ w_mult) {
    int idx = blockIdx.x * blockDim.x + threadIdx.x;
    if (idx >= B_ * E_ * Q_) return;
    int q = idx % Q_;
    int e = (idx / Q_) % E_;
    int b = idx / (Q_ * E_);
    g_qmT[idx] = question[((size_t)b * Q_ + q) * E_ + e] * w_mult[e];
}

__global__ __launch_bounds__(256) void sgemm128_kernel(
    const float* __restrict__ A, const float* __restrict__ Bm, float* __restrict__ C,
    int M, int N, int K,
    size_t sA, size_t sB, size_t sC,
    const float* __restrict__ rowAdd, int sRow,
    const float* __restrict__ colAdd, int sCol) {
    const int BK = 16, TM = 8, TN = 8;
    __shared__ float As[BK][128];
    __shared__ float Bs[BK][128];
    int bz = blockIdx.z;
    A += bz * sA; Bm += bz * sB; C += bz * sC;
    int block_row = blockIdx.y * 128;
    int block_col = blockIdx.x * 128;
    int tid = threadIdx.x;
    int tx = tid & 15, ty = tid >> 4;
    float acc[TM][TN];
    #pragma unroll
    for (int i = 0; i < TM; i++)
        #pragma unroll
        for (int j = 0; j < TN; j++) acc[i][j] = 0.f;
    for (int k0 = 0; k0 < K; k0 += BK) {
        #pragma unroll
        for (int i = 0; i < 8; i++) {
            int idx = tid + i * 256;
            int m = idx >> 4, k = idx & 15;
            As[k][m] = A[(size_t)(block_row + m) * K + k0 + k];
        }
        #pragma unroll
        for (int i = 0; i < 8; i++) {
            int idx = tid + i * 256;
            int k = idx >> 7, n = idx & 127;
            Bs[k][n] = Bm[(size_t)(k0 + k) * N + block_col + n];
        }
        __syncthreads();
        #pragma unroll
        for (int k = 0; k < BK; k++) {
            float a[TM], bf[TN];
            #pragma unroll
            for (int i = 0; i < TM; i++) a[i] = As[k][ty * TM + i];
            #pragma unroll
            for (int j = 0; j < TN; j++) bf[j] = Bs[k][tx * TN + j];
            #pragma unroll
            for (int i = 0; i < TM; i++)
                #pragma unroll
                for (int j = 0; j < TN; j++) acc[i][j] += a[i] * bf[j];
        }
        __syncthreads();
    }
    #pragma unroll
    for (int i = 0; i < TM; i++) {
        int row = block_row + ty * TM + i;
        float radd = rowAdd ? rowAdd[bz * sRow + row] : 0.f;
        #pragma unroll
        for (int j = 0; j < TN; j++) {
            int col = block_col + tx * TN + j;
            C[(size_t)row * N + col] = acc[i][j] + radd + (colAdd ? colAdd[bz * sCol + col] : 0.f);
        }
    }
}

__global__ void softmax_q_kernel() {
    int row = blockIdx.x;
    float* s = g_sim + (size_t)row * Q_;
    int t = threadIdx.x;
    float v = s[t];
    __shared__ float sh[Q_];
    sh[t] = v; __syncthreads();
    #pragma unroll
    for (int o = 64; o > 0; o >>= 1) { if (t < o) sh[t] = fmaxf(sh[t], sh[t + o]); __syncthreads(); }
    float m = sh[0]; __syncthreads();
    if (t == 0) g_rowmax[row] = m;
    float e = expf(v - m);
    sh[t] = e; __syncthreads();
    #pragma unroll
    for (int o = 64; o > 0; o >>= 1) { if (t < o) sh[t] += sh[t + o]; __syncthreads(); }
    s[t] = e / sh[0];
}

__global__ void q2c_kernel(const float* __restrict__ context) {
    int b = blockIdx.x;
    __shared__ float w[C_];
    __shared__ float red[256];
    int t = threadIdx.x;
    const float* rm = g_rowmax + b * C_;
    float mx = -1e30f;
    for (int c = t; c < C_; c += 256) mx = fmaxf(mx, rm[c]);
    red[t] = mx; __syncthreads();
    #pragma unroll
    for (int o = 128; o > 0; o >>= 1) { if (t < o) red[t] = fmaxf(red[t], red[t + o]); __syncthreads(); }
    mx = red[0]; __syncthreads();
    float sum = 0.f;
    for (int c = t; c < C_; c += 256) { float e = expf(rm[c] - mx); w[c] = e; sum += e; }
    red[t] = sum; __syncthreads();
    #pragma unroll
    for (int o = 128; o > 0; o >>= 1) { if (t < o) red[t] += red[t + o]; __syncthreads(); }
    float inv = 1.f / red[0]; __syncthreads();
    const float* ctx = context + (size_t)b * C_ * E_;
    for (int e0 = t; e0 < E_; e0 += 256) {
        float acc = 0.f;
        #pragma unroll 4
        for (int c = 0; c < C_; c++) acc += w[c] * ctx[(size_t)c * E_ + e0];
        g_q2c[b * E_ + e0] = acc * inv;
    }
}

// attended (fp32) -> split bf16 A1' = [hi | lo | hi], ld = 3*FE
__global__ void build_attended_split_kernel(const float* __restrict__ context) {
    size_t idx = (size_t)blockIdx.x * blockDim.x + threadIdx.x;
    if (idx >= (size_t)B_ * C_ * E_) return;
    int e = (int)(idx % E_);
    size_t bc = idx / E_;
    int b = (int)(bc / C_);
    float ctx = context[idx];
    float cq = g_c2q[idx];
    float qc = g_q2c[b * E_ + e];
    float vals[4] = { ctx, cq, ctx * cq, ctx * qc };
    __nv_bfloat16* row = g_A1 + bc * (size_t)(3 * FE);
    #pragma unroll
    for (int j = 0; j < 4; j++) {
        int col = j * E_ + e;
        __nv_bfloat16 hi = __float2bfloat16(vals[j]);
        __nv_bfloat16 lo = __float2bfloat16(vals[j] - __bfloat162float(hi));
        row[col] = hi;
        row[FE + col] = lo;
        row[2 * FE + col] = hi;
    }
}

// W (fp32, [K x N] row-major) -> B'^T (bf16, [N x 3K]) = [hi | hi | lo]
__global__ void split_w_kernel(const float* __restrict__ W, __nv_bfloat16* __restrict__ Bt,
                               int K, int N) {
    int idx = blockIdx.x * blockDim.x + threadIdx.x;
    if (idx >= K * N) return;
    int k = idx % K;
    int n = idx / K;
    float v = W[(size_t)k * N + n];
    __nv_bfloat16 hi = __float2bfloat16(v);
    __nv_bfloat16 lo = __float2bfloat16(v - __bfloat162float(hi));
    __nv_bfloat16* row = Bt + (size_t)n * (3 * K);
    row[k] = hi;
    row[K + k] = hi;
    row[2 * K + k] = lo;
}

// ---------------- mma.sync bf16 GEMM: 128x128 tile, BK=32, double-buffered cp.async ----------------
// C[M,N] = A'[M,Kp] @ B'^T[N,Kp]^T ; epilogue: (acc + colAdd[n]) * rowMul[m]
// outSplit!=null: write bf16 [hi|lo|hi] rows of width 3*splitK ; else fp32 (+relu)
#define LDA 40   // 32 + 8 pad elements; row stride 80B -> conflict-free ldmatrix

__global__ __launch_bounds__(256, 2) void mma_gemm_kernel(
    const __nv_bfloat16* __restrict__ A, const __nv_bfloat16* __restrict__ Bt,
    int N, int Kp,
    const float* __restrict__ colAdd, const float* __restrict__ rowMul,
    float* __restrict__ outF, __nv_bfloat16* __restrict__ outSplit, int splitK, int relu) {
    __shared__ __nv_bfloat16 sA[2][128 * LDA];
    __shared__ __nv_bfloat16 sB[2][128 * LDA];
    int tid = threadIdx.x;
    int wid = tid >> 5, lane = tid & 31;
    int warpM = wid >> 2, warpN = wid & 3;            // 2 x 4 warps -> 64 x 32 per warp
    int mrow0 = blockIdx.y * 128;
    int ncol0 = blockIdx.x * 128;
    const __nv_bfloat16* Ag = A + (size_t)mrow0 * Kp;
    const __nv_bfloat16* Bg = Bt + (size_t)ncol0 * Kp;

    float acc[4][4][4];
    #pragma unroll
    for (int mi = 0; mi < 4; mi++)
        #pragma unroll
        for (int nj = 0; nj < 4; nj++)
            #pragma unroll
            for (int r = 0; r < 4; r++) acc[mi][nj][r] = 0.f;

    // per-thread load slots: 1024 16B-chunks per stage (A:512, B:512), 4 per thread
    int ldr = (tid * 2) >> 2;        // rows advance: idx = tid*? -- computed below instead
    (void)ldr;

    auto load_stage = [&](int ch, int buf) {
        int k0 = ch * 32;
        uint32_t abase = smem_u32(&sA[buf][0]);
        uint32_t bbase = smem_u32(&sB[buf][0]);
        #pragma unroll
        for (int j = 0; j < 2; j++) {
            int idx = tid + j * 256;                 // 0..511
            int r = idx >> 2, s = idx & 3;
            CP_ASYNC16(abase + (uint32_t)(r * LDA + s * 8) * 2, Ag + (size_t)r * Kp + k0 + s * 8);
        }
        #pragma unroll
        for (int j = 0; j < 2; j++) {
            int idx = tid + j * 256;
            int r = idx >> 2, s = idx & 3;
            CP_ASYNC16(bbase + (uint32_t)(r * LDA + s * 8) * 2, Bg + (size_t)r * Kp + k0 + s * 8);
        }
        CP_COMMIT();
    };

    int nCh = Kp >> 5;
    load_stage(0, 0);
    for (int i = 0; i < nCh; i++) {
        if (i + 1 < nCh) {
            load_stage(i + 1, (i + 1) & 1);
            asm volatile("cp.async.wait_group 1;" ::: "memory");
        } else {
            asm volatile("cp.async.wait_group 0;" ::: "memory");
        }
        __syncthreads();
        int buf = i & 1;
        uint32_t abase = smem_u32(&sA[buf][0]);
        uint32_t bbase = smem_u32(&sB[buf][0]);
        #pragma unroll
        for (int ks = 0; ks < 2; ks++) {
            uint32_t afrag[4][4];
            uint32_t bfrag[4][2];
            int arow = warpM * 64 + (lane & 15);
            int acol = ks * 16 + (lane >> 4) * 8;
            #pragma unroll
            for (int mi = 0; mi < 4; mi++) {
                uint32_t addr = abase + (uint32_t)((arow + mi * 16) * LDA + acol) * 2;
                asm volatile("ldmatrix.sync.aligned.m8n8.x4.shared.b16 {%0,%1,%2,%3}, [%4];"
                    : "=r"(afrag[mi][0]), "=r"(afrag[mi][1]), "=r"(afrag[mi][2]), "=r"(afrag[mi][3])
                    : "r"(addr));
            }
            int brow = warpN * 32 + (lane & 7) + ((lane >> 4) << 3);
            int bcol = ks * 16 + ((lane >> 3) & 1) * 8;
            #pragma unroll
            for (int p = 0; p < 2; p++) {
                uint32_t addr = bbase + (uint32_t)((brow + p * 16) * LDA + bcol) * 2;
                asm volatile("ldmatrix.sync.aligned.m8n8.x4.shared.b16 {%0,%1,%2,%3}, [%4];"
                    : "=r"(bfrag[2 * p][0]), "=r"(bfrag[2 * p][1]),
                      "=r"(bfrag[2 * p + 1][0]), "=r"(bfrag[2 * p + 1][1])
                    : "r"(addr));
            }
            #pragma unroll
            for (int mi = 0; mi < 4; mi++)
                #pragma unroll
                for (int nj = 0; nj < 4; nj++)
                    asm volatile(
                        "mma.sync.aligned.m16n8k16.row.col.f32.bf16.bf16.f32 "
                        "{%0,%1,%2,%3}, {%4,%5,%6,%7}, {%8,%9}, {%0,%1,%2,%3};"
                        : "+f"(acc[mi][nj][0]), "+f"(acc[mi][nj][1]),
                          "+f"(acc[mi][nj][2]), "+f"(acc[mi][nj][3])
                        : "r"(afrag[mi][0]), "r"(afrag[mi][1]), "r"(afrag[mi][2]), "r"(afrag[mi][3]),
                          "r"(bfrag[nj][0]), "r"(bfrag[nj][1]));
        }
        __syncthreads();
    }

    // epilogue straight from register fragments
    #pragma unroll
    for (int mi = 0; mi < 4; mi++) {
        #pragma unroll
        for (int half = 0; half < 2; half++) {
            int m = mrow0 + warpM * 64 + mi * 16 + half * 8 + (lane >> 2);
            float rmul = rowMul ? rowMul[m] : 1.f;
            #pragma unroll
            for (int nj = 0; nj < 4; nj++) {
                int n = ncol0 + warpN * 32 + nj * 8 + (lane & 3) * 2;
                float v0 = (acc[mi][nj][half * 2 + 0] + colAdd[n]) * rmul;
                float v1 = (acc[mi][nj][half * 2 + 1] + colAdd[n + 1]) * rmul;
                if (outSplit) {
                    __nv_bfloat16* row = outSplit + (size_t)m * (3 * splitK);
                    __nv_bfloat16 h0 = __float2bfloat16(v0);
                    __nv_bfloat16 l0 = __float2bfloat16(v0 - __bfloat162float(h0));
                    __nv_bfloat16 h1 = __float2bfloat16(v1);
                    __nv_bfloat16 l1 = __float2bfloat16(v1 - __bfloat162float(h1));
                    row[n] = h0;               row[n + 1] = h1;
                    row[splitK + n] = l0;      row[splitK + n + 1] = l1;
                    row[2 * splitK + n] = h0;  row[2 * splitK + n + 1] = h1;
                } else {
                    if (relu) { v0 = fmaxf(v0, 0.f); v1 = fmaxf(v1, 0.f); }
                    outF[(size_t)m * N + n] = v0;
                    outF[(size_t)m * N + n + 1] = v1;
                }
            }
        }
    }
}

// ---------------- launch ----------------
extern "C" void kernel_launch(void* const* d_in, const int* in_sizes, int n_in,
                              void* d_out, int out_size) {
    const float* context    = (const float*)d_in[0];
    const float* question   = (const float*)d_in[1];
    const float* mask       = (const float*)d_in[2];
    const float* w_question = (const float*)d_in[3];
    const float* w_context  = (const float*)d_in[4];
    const float* w_multiple = (const float*)d_in[5];
    const float* W1         = (const float*)d_in[6];
    const float* b1         = (const float*)d_in[7];
    const float* W2         = (const float*)d_in[8];
    const float* b2         = (const float*)d_in[9];
    float* out = (float*)d_out;

    float *p_qw, *p_cw, *p_qmT, *p_sim, *p_c2q;
    __nv_bfloat16 *p_A1, *p_B1, *p_A2, *p_B2;
    cudaGetSymbolAddress((void**)&p_qw, g_qw);
    cudaGetSymbolAddress((void**)&p_cw, g_cw);
    cudaGetSymbolAddress((void**)&p_qmT, g_qmT);
    cudaGetSymbolAddress((void**)&p_sim, g_sim);
    cudaGetSymbolAddress((void**)&p_c2q, g_c2q);
    cudaGetSymbolAddress((void**)&p_A1, g_A1);
    cudaGetSymbolAddress((void**)&p_B1, g_B1);
    cudaGetSymbolAddress((void**)&p_A2, g_A2);
    cudaGetSymbolAddress((void**)&p_B2, g_B2);

    // weight splits (independent of attention chain)
    split_w_kernel<<<(FE * H_ + 255) / 256, 256>>>(W1, p_B1, FE, H_);
    split_w_kernel<<<(H_ * FE + 255) / 256, 256>>>(W2, p_B2, H_, FE);

    // attention front-end (scalar)
    dot_w_kernel<<<B_ * Q_, 128>>>(question, w_question, p_qw, E_);
    dot_w_kernel<<<B_ * C_, 128>>>(context, w_context, p_cw, E_);
    build_qmT_kernel<<<(B_ * E_ * Q_ + 255) / 256, 256>>>(question, w_multiple);
    {
        dim3 grid(Q_ / 128, C_ / 128, B_);
        sgemm128_kernel<<<grid, 256>>>(context, p_qmT, p_sim, C_, Q_, E_,
                                       (size_t)C_ * E_, (size_t)E_ * Q_, (size_t)C_ * Q_,
                                       p_cw, C_, p_qw, Q_);
    }
    softmax_q_kernel<<<B_ * C_, Q_>>>();
    {
        dim3 grid(E_ / 128, C_ / 128, B_);
        sgemm128_kernel<<<grid, 256>>>(p_sim, question, p_c2q, C_, E_, Q_,
                                       (size_t)C_ * Q_, (size_t)Q_ * E_, (size_t)C_ * E_,
                                       nullptr, 0, nullptr, 0);
    }
    q2c_kernel<<<B_, 256>>>(context);
    build_attended_split_kernel<<<(B_ * C_ * E_ + 255) / 256, 256>>>(context);

    // MLP1: [8192 x 6144] @ [6144 x 1024]^T-layout -> split bf16 A2'
    {
        dim3 grid(H_ / 128, (B_ * C_) / 128);
        mma_gemm_kernel<<<grid, 256>>>(p_A1, p_B1, H_, 3 * FE,
                                       b1, mask, nullptr, p_A2, H_, 0);
    }
    // MLP2: [8192 x 3072] @ [3072 x 2048]^T-layout -> fp32 out with relu
    {
        dim3 grid(FE / 128, (B_ * C_) / 128);
        mma_gemm_kernel<<<grid, 256>>>(p_A2, p_B2, FE, 3 * H_,
                                       b2, mask, out, nullptr, 0, 1);
    }
}

// round 6
// speedup vs baseline: 2.4966x; 1.2294x over previous
#include <cuda_runtime.h>
#include <cuda_bf16.h>
#include <cstdint>
#include <cstddef>

#define B_ 8
#define C_ 1024
#define Q_ 128
#define E_ 512
#define H_ 1024
#define FE (4 * E_)   // 2048

// ---------------- helpers ----------------
__device__ __forceinline__ uint32_t smem_u32(const void* p) {
    uint32_t a;
    asm("{ .reg .u64 t; cvta.to.shared.u64 t, %1; cvt.u32.u64 %0, t; }" : "=r"(a) : "l"(p));
    return a;
}
#define CP_ASYNC16(dst, src) \
    asm volatile("cp.async.cg.shared.global [%0], [%1], 16;" :: "r"(dst), "l"(src) : "memory")
#define CP_COMMIT() asm volatile("cp.async.commit_group;" ::: "memory")

__device__ __forceinline__ void split_bf16(float v, __nv_bfloat16& hi, __nv_bfloat16& lo) {
    hi = __float2bfloat16(v);
    lo = __float2bfloat16(v - __bfloat162float(hi));
}

// ---------------- scratch ----------------
__device__ float g_qw[B_ * Q_];
__device__ float g_cw[B_ * C_];
__device__ float g_sim[B_ * C_ * Q_];
__device__ float g_rowmax[B_ * C_];
__device__ float g_cwgt[B_ * C_];
__device__ float g_c2q[B_ * C_ * E_];
__device__ float g_q2c[B_ * E_];
// split operands: A-style = [hi | lo | hi], B-style = [hi | hi | lo]
__device__ __nv_bfloat16 g_ctxS[(size_t)B_ * C_ * 3 * E_];   // sim A
__device__ __nv_bfloat16 g_qmS[(size_t)B_ * Q_ * 3 * E_];    // sim B (question*w_mult)
__device__ __nv_bfloat16 g_ps[(size_t)B_ * C_ * 3 * Q_];     // c2q A (probs)
__device__ __nv_bfloat16 g_qTs[(size_t)B_ * E_ * 3 * Q_];    // c2q B (question^T)
__device__ __nv_bfloat16 g_A1[(size_t)B_ * C_ * 3 * FE];     // MLP1 A (attended)
__device__ __nv_bfloat16 g_B1[(size_t)H_ * 3 * FE];          // MLP1 B (W1^T)
__device__ __nv_bfloat16 g_A2[(size_t)B_ * C_ * 3 * H_];     // MLP2 A (h)
__device__ __nv_bfloat16 g_B2[(size_t)FE * 3 * H_];          // MLP2 B (W2^T)

// ---------------- fused preprocess: dot + split ----------------
// context row: g_cw (dot w_context), g_ctxS = [hi|lo|hi]
__global__ void ctx_pre_kernel(const float* __restrict__ context,
                               const float* __restrict__ w_context) {
    int row = blockIdx.x;                    // b*C + c
    const float4* x4 = (const float4*)(context + (size_t)row * E_);
    const float4* w4 = (const float4*)w_context;
    __nv_bfloat16* o = g_ctxS + (size_t)row * (3 * E_);
    float s = 0.f;
    for (int i = threadIdx.x; i < E_ / 4; i += 128) {
        float4 xv = x4[i], wv = w4[i];
        s += xv.x * wv.x + xv.y * wv.y + xv.z * wv.z + xv.w * wv.w;
        float v[4] = { xv.x, xv.y, xv.z, xv.w };
        #pragma unroll
        for (int j = 0; j < 4; j++) {
            __nv_bfloat16 hi, lo; split_bf16(v[j], hi, lo);
            int e = i * 4 + j;
            o[e] = hi; o[E_ + e] = lo; o[2 * E_ + e] = hi;
        }
    }
    __shared__ float red[4];
    #pragma unroll
    for (int off = 16; off > 0; off >>= 1) s += __shfl_down_sync(0xffffffffu, s, off);
    if ((threadIdx.x & 31) == 0) red[threadIdx.x >> 5] = s;
    __syncthreads();
    if (threadIdx.x == 0) g_cw[row] = red[0] + red[1] + red[2] + red[3];
}

// question row: g_qw (dot w_question), g_qmS = [hi|hi|lo] of question*w_mult
__global__ void q_pre_kernel(const float* __restrict__ question,
                             const float* __restrict__ w_question,
                             const float* __restrict__ w_multiple) {
    int row = blockIdx.x;                    // b*Q + q
    const float4* x4 = (const float4*)(question + (size_t)row * E_);
    const float4* wq4 = (const float4*)w_question;
    const float4* wm4 = (const float4*)w_multiple;
    __nv_bfloat16* o = g_qmS + (size_t)row * (3 * E_);
    float s = 0.f;
    for (int i = threadIdx.x; i < E_ / 4; i += 128) {
        float4 xv = x4[i], wq = wq4[i], wm = wm4[i];
        s += xv.x * wq.x + xv.y * wq.y + xv.z * wq.z + xv.w * wq.w;
        float v[4] = { xv.x * wm.x, xv.y * wm.y, xv.z * wm.z, xv.w * wm.w };
        #pragma unroll
        for (int j = 0; j < 4; j++) {
            __nv_bfloat16 hi, lo; split_bf16(v[j], hi, lo);
            int e = i * 4 + j;
            o[e] = hi; o[E_ + e] = hi; o[2 * E_ + e] = lo;
        }
    }
    __shared__ float red[4];
    #pragma unroll
    for (int off = 16; off > 0; off >>= 1) s += __shfl_down_sync(0xffffffffu, s, off);
    if ((threadIdx.x & 31) == 0) red[threadIdx.x >> 5] = s;
    __syncthreads();
    if (threadIdx.x == 0) g_qw[row] = red[0] + red[1] + red[2] + red[3];
}

// question^T split for c2q B operand: g_qTs[b][e][3Q] = [hi|hi|lo]
__global__ void qT_split_kernel(const float* __restrict__ question) {
    __shared__ float tile[32][33];
    int b = blockIdx.z;
    int e0 = blockIdx.x * 32, q0 = blockIdx.y * 32;
    int tx = threadIdx.x, ty = threadIdx.y;      // (32, 8)
    #pragma unroll
    for (int j = 0; j < 4; j++) {
        int qi = ty * 4 + j;
        tile[qi][tx] = question[((size_t)b * Q_ + q0 + qi) * E_ + e0 + tx];
    }
    __syncthreads();
    #pragma unroll
    for (int j = 0; j < 4; j++) {
        int ei = ty * 4 + j;
        float v = tile[tx][ei];
        __nv_bfloat16 hi, lo; split_bf16(v, hi, lo);
        __nv_bfloat16* r = g_qTs + ((size_t)b * E_ + e0 + ei) * (3 * Q_);
        r[q0 + tx] = hi; r[Q_ + q0 + tx] = hi; r[2 * Q_ + q0 + tx] = lo;
    }
}

// W (fp32, [K x N] row-major) -> B' (bf16, [N x 3K]) = [hi | hi | lo]
__global__ void split_w_kernel(const float* __restrict__ W, __nv_bfloat16* __restrict__ Bt,
                               int K, int N) {
    int idx = blockIdx.x * blockDim.x + threadIdx.x;
    if (idx >= K * N) return;
    int k = idx % K;
    int n = idx / K;
    float v = W[(size_t)k * N + n];
    __nv_bfloat16 hi, lo; split_bf16(v, hi, lo);
    __nv_bfloat16* row = Bt + (size_t)n * (3 * K);
    row[k] = hi; row[K + k] = hi; row[2 * K + k] = lo;
}

// ---------------- softmax over q: probs -> split bf16, keep rowmax ----------------
__global__ void softmax_q_kernel() {
    int row = blockIdx.x;                    // b*C + c
    const float* s = g_sim + (size_t)row * Q_;
    int t = threadIdx.x;                     // 128
    float v = s[t];
    __shared__ float sh[Q_];
    sh[t] = v; __syncthreads();
    #pragma unroll
    for (int o = 64; o > 0; o >>= 1) { if (t < o) sh[t] = fmaxf(sh[t], sh[t + o]); __syncthreads(); }
    float m = sh[0]; __syncthreads();
    if (t == 0) g_rowmax[row] = m;
    float e = expf(v - m);
    sh[t] = e; __syncthreads();
    #pragma unroll
    for (int o = 64; o > 0; o >>= 1) { if (t < o) sh[t] += sh[t + o]; __syncthreads(); }
    float p = e / sh[0];
    __nv_bfloat16 hi, lo; split_bf16(p, hi, lo);
    __nv_bfloat16* r = g_ps + (size_t)row * (3 * Q_);
    r[t] = hi; r[Q_ + t] = lo; r[2 * Q_ + t] = hi;
}

// ---------------- q2c: (1) per-batch softmax weights, (2) weighted sum ----------------
__global__ void q2c_w_kernel() {
    int b = blockIdx.x;
    int t = threadIdx.x;                     // 256
    __shared__ float red[256];
    const float* rm = g_rowmax + b * C_;
    float mx = -1e30f;
    for (int c = t; c < C_; c += 256) mx = fmaxf(mx, rm[c]);
    red[t] = mx; __syncthreads();
    #pragma unroll
    for (int o = 128; o > 0; o >>= 1) { if (t < o) red[t] = fmaxf(red[t], red[t + o]); __syncthreads(); }
    mx = red[0]; __syncthreads();
    float sum = 0.f;
    for (int c = t; c < C_; c += 256) { float e = expf(rm[c] - mx); g_cwgt[b * C_ + c] = e; sum += e; }
    red[t] = sum; __syncthreads();
    #pragma unroll
    for (int o = 128; o > 0; o >>= 1) { if (t < o) red[t] += red[t + o]; __syncthreads(); }
    float inv = 1.f / red[0];
    for (int c = t; c < C_; c += 256) g_cwgt[b * C_ + c] *= inv;
}

__global__ void q2c_sum_kernel(const float* __restrict__ context) {
    int b = blockIdx.y;
    int e = blockIdx.x * 256 + threadIdx.x;  // E=512 -> grid.x=2
    __shared__ float w[C_];
    for (int c = threadIdx.x; c < C_; c += 256) w[c] = g_cwgt[b * C_ + c];
    __syncthreads();
    const float* ctx = context + (size_t)b * C_ * E_ + e;
    float acc = 0.f;
    #pragma unroll 8
    for (int c = 0; c < C_; c++) acc += w[c] * ctx[(size_t)c * E_];
    g_q2c[b * E_ + e] = acc;
}

// ---------------- attended (fp32 parts) -> split bf16 A1' = [hi|lo|hi] ----------------
__global__ void build_attended_split_kernel(const float* __restrict__ context) {
    size_t idx = (size_t)blockIdx.x * blockDim.x + threadIdx.x;
    if (idx >= (size_t)B_ * C_ * E_) return;
    int e = (int)(idx % E_);
    size_t bc = idx / E_;
    int b = (int)(bc / C_);
    float ctx = context[idx];
    float cq = g_c2q[idx];
    float qc = g_q2c[b * E_ + e];
    float vals[4] = { ctx, cq, ctx * cq, ctx * qc };
    __nv_bfloat16* row = g_A1 + bc * (size_t)(3 * FE);
    #pragma unroll
    for (int j = 0; j < 4; j++) {
        int col = j * E_ + e;
        __nv_bfloat16 hi, lo; split_bf16(vals[j], hi, lo);
        row[col] = hi;
        row[FE + col] = lo;
        row[2 * FE + col] = hi;
    }
}

// ---------------- generic mma.sync bf16 GEMM ----------------
// C[bz] = A'[bz](M x Kp) @ B'[bz](N x Kp)^T
// epilogue: v = (acc + rowAdd[bz*sRow+m] + colAdd[bz*sCol+n]) * rowMul[m]; relu optional
// outSplit!=null: write bf16 [hi|lo|hi] rows of width 3*splitK ; else fp32 at outF
#define LDA 40                         // 32 + 8 pad; conflict-free ldmatrix
#define STAGE_BYTES (2 * 128 * LDA * 2)   // A + B per stage = 20480
#define SMEM_TOTAL (3 * STAGE_BYTES)      // 61440

__global__ __launch_bounds__(256, 2) void mma_gemm_kernel(
    const __nv_bfloat16* __restrict__ A, const __nv_bfloat16* __restrict__ Bt,
    int N, int Kp,
    size_t sA, size_t sB, size_t sO,
    const float* __restrict__ rowAdd, int sRow,
    const float* __restrict__ colAdd, int sCol,
    const float* __restrict__ rowMul,
    float* __restrict__ outF, __nv_bfloat16* __restrict__ outSplit, int splitK, int relu) {
    extern __shared__ char smem[];
    uint32_t sb = smem_u32(smem);
    int tid = threadIdx.x;
    int wid = tid >> 5, lane = tid & 31;
    int warpM = wid >> 2, warpN = wid & 3;            // 2 x 4 warps -> 64 x 32 per warp
    int bz = blockIdx.z;
    int mrow0 = blockIdx.y * 128;
    int ncol0 = blockIdx.x * 128;
    const __nv_bfloat16* Ag = A + bz * sA + (size_t)mrow0 * Kp;
    const __nv_bfloat16* Bg = Bt + bz * sB + (size_t)ncol0 * Kp;

    float acc[4][4][4];
    #pragma unroll
    for (int mi = 0; mi < 4; mi++)
        #pragma unroll
        for (int nj = 0; nj < 4; nj++)
            #pragma unroll
            for (int r = 0; r < 4; r++) acc[mi][nj][r] = 0.f;

    auto load_stage = [&](int ch, int st) {
        int k0 = ch * 32;
        uint32_t abase = sb + st * STAGE_BYTES;
        uint32_t bbase = abase + 128 * LDA * 2;
        #pragma unroll
        for (int j = 0; j < 2; j++) {
            int idx = tid + j * 256;                 // 0..511
            int r = idx >> 2, s = idx & 3;
            CP_ASYNC16(abase + (uint32_t)(r * LDA + s * 8) * 2, Ag + (size_t)r * Kp + k0 + s * 8);
        }
        #pragma unroll
        for (int j = 0; j < 2; j++) {
            int idx = tid + j * 256;
            int r = idx >> 2, s = idx & 3;
            CP_ASYNC16(bbase + (uint32_t)(r * LDA + s * 8) * 2, Bg + (size_t)r * Kp + k0 + s * 8);
        }
        CP_COMMIT();
    };

    int nCh = Kp >> 5;
    load_stage(0, 0);
    if (nCh > 1) load_stage(1, 1);
    int st = 0;
    for (int i = 0; i < nCh; i++) {
        if (i + 1 < nCh) {
            asm volatile("cp.async.wait_group 1;" ::: "memory");
        } else {
            asm volatile("cp.async.wait_group 0;" ::: "memory");
        }
        __syncthreads();
        if (i + 2 < nCh) {
            int nst = st + 2; if (nst >= 3) nst -= 3;
            load_stage(i + 2, nst);
        }
        uint32_t abase = sb + st * STAGE_BYTES;
        uint32_t bbase = abase + 128 * LDA * 2;
        #pragma unroll
        for (int ks = 0; ks < 2; ks++) {
            uint32_t afrag[4][4];
            uint32_t bfrag[4][2];
            int arow = warpM * 64 + (lane & 15);
            int acol = ks * 16 + (lane >> 4) * 8;
            #pragma unroll
            for (int mi = 0; mi < 4; mi++) {
                uint32_t addr = abase + (uint32_t)((arow + mi * 16) * LDA + acol) * 2;
                asm volatile("ldmatrix.sync.aligned.m8n8.x4.shared.b16 {%0,%1,%2,%3}, [%4];"
                    : "=r"(afrag[mi][0]), "=r"(afrag[mi][1]), "=r"(afrag[mi][2]), "=r"(afrag[mi][3])
                    : "r"(addr));
            }
            int brow = warpN * 32 + (lane & 7) + ((lane >> 4) << 3);
            int bcol = ks * 16 + ((lane >> 3) & 1) * 8;
            #pragma unroll
            for (int p = 0; p < 2; p++) {
                uint32_t addr = bbase + (uint32_t)((brow + p * 16) * LDA + bcol) * 2;
                asm volatile("ldmatrix.sync.aligned.m8n8.x4.shared.b16 {%0,%1,%2,%3}, [%4];"
                    : "=r"(bfrag[2 * p][0]), "=r"(bfrag[2 * p][1]),
                      "=r"(bfrag[2 * p + 1][0]), "=r"(bfrag[2 * p + 1][1])
                    : "r"(addr));
            }
            #pragma unroll
            for (int mi = 0; mi < 4; mi++)
                #pragma unroll
                for (int nj = 0; nj < 4; nj++)
                    asm volatile(
                        "mma.sync.aligned.m16n8k16.row.col.f32.bf16.bf16.f32 "
                        "{%0,%1,%2,%3}, {%4,%5,%6,%7}, {%8,%9}, {%0,%1,%2,%3};"
                        : "+f"(acc[mi][nj][0]), "+f"(acc[mi][nj][1]),
                          "+f"(acc[mi][nj][2]), "+f"(acc[mi][nj][3])
                        : "r"(afrag[mi][0]), "r"(afrag[mi][1]), "r"(afrag[mi][2]), "r"(afrag[mi][3]),
                          "r"(bfrag[nj][0]), "r"(bfrag[nj][1]));
        }
        __syncthreads();
        if (++st == 3) st = 0;
    }

    // epilogue straight from register fragments
    #pragma unroll
    for (int mi = 0; mi < 4; mi++) {
        #pragma unroll
        for (int half = 0; half < 2; half++) {
            int m = mrow0 + warpM * 64 + mi * 16 + half * 8 + (lane >> 2);
            float ra = rowAdd ? rowAdd[bz * sRow + m] : 0.f;
            float rmul = rowMul ? rowMul[m] : 1.f;
            #pragma unroll
            for (int nj = 0; nj < 4; nj++) {
                int n = ncol0 + warpN * 32 + nj * 8 + (lane & 3) * 2;
                float ca0 = colAdd ? colAdd[bz * sCol + n] : 0.f;
                float ca1 = colAdd ? colAdd[bz * sCol + n + 1] : 0.f;
                float v0 = (acc[mi][nj][half * 2 + 0] + ra + ca0) * rmul;
                float v1 = (acc[mi][nj][half * 2 + 1] + ra + ca1) * rmul;
                if (outSplit) {
                    __nv_bfloat16* row = outSplit + (size_t)m * (3 * splitK);
                    __nv_bfloat16 h0, l0, h1, l1;
                    split_bf16(v0, h0, l0);
                    split_bf16(v1, h1, l1);
                    row[n] = h0;               row[n + 1] = h1;
                    row[splitK + n] = l0;      row[splitK + n + 1] = l1;
                    row[2 * splitK + n] = h0;  row[2 * splitK + n + 1] = h1;
                } else {
                    if (relu) { v0 = fmaxf(v0, 0.f); v1 = fmaxf(v1, 0.f); }
                    float* o = outF + bz * sO;
                    o[(size_t)m * N + n] = v0;
                    o[(size_t)m * N + n + 1] = v1;
                }
            }
        }
    }
}

// ---------------- launch ----------------
extern "C" void kernel_launch(void* const* d_in, const int* in_sizes, int n_in,
                              void* d_out, int out_size) {
    const float* context    = (const float*)d_in[0];
    const float* question   = (const float*)d_in[1];
    const float* mask       = (const float*)d_in[2];
    const float* w_question = (const float*)d_in[3];
    const float* w_context  = (const float*)d_in[4];
    const float* w_multiple = (const float*)d_in[5];
    const float* W1         = (const float*)d_in[6];
    const float* b1         = (const float*)d_in[7];
    const float* W2         = (const float*)d_in[8];
    const float* b2         = (const float*)d_in[9];
    float* out = (float*)d_out;

    float *p_sim, *p_c2q, *p_qw, *p_cw;
    __nv_bfloat16 *p_ctxS, *p_qmS, *p_ps, *p_qTs, *p_A1, *p_B1, *p_A2, *p_B2;
    cudaGetSymbolAddress((void**)&p_sim, g_sim);
    cudaGetSymbolAddress((void**)&p_c2q, g_c2q);
    cudaGetSymbolAddress((void**)&p_qw, g_qw);
    cudaGetSymbolAddress((void**)&p_cw, g_cw);
    cudaGetSymbolAddress((void**)&p_ctxS, g_ctxS);
    cudaGetSymbolAddress((void**)&p_qmS, g_qmS);
    cudaGetSymbolAddress((void**)&p_ps, g_ps);
    cudaGetSymbolAddress((void**)&p_qTs, g_qTs);
    cudaGetSymbolAddress((void**)&p_A1, g_A1);
    cudaGetSymbolAddress((void**)&p_B1, g_B1);
    cudaGetSymbolAddress((void**)&p_A2, g_A2);
    cudaGetSymbolAddress((void**)&p_B2, g_B2);

    cudaFuncSetAttribute(mma_gemm_kernel, cudaFuncAttributeMaxDynamicSharedMemorySize,
                         SMEM_TOTAL);

    // weight splits (independent)
    split_w_kernel<<<(FE * H_ + 255) / 256, 256>>>(W1, p_B1, FE, H_);
    split_w_kernel<<<(H_ * FE + 255) / 256, 256>>>(W2, p_B2, H_, FE);

    // preprocess: dots + splits
    ctx_pre_kernel<<<B_ * C_, 128>>>(context, w_context);
    q_pre_kernel<<<B_ * Q_, 128>>>(question, w_question, w_multiple);
    {
        dim3 grid(E_ / 32, Q_ / 32, B_);
        qT_split_kernel<<<grid, dim3(32, 8)>>>(question);
    }

    // sim = context @ (question*w_mult)^T + cw[row] + qw[col]   (tensor)
    {
        dim3 grid(Q_ / 128, C_ / 128, B_);
        mma_gemm_kernel<<<grid, 256, SMEM_TOTAL>>>(
            p_ctxS, p_qmS, Q_, 3 * E_,
            (size_t)C_ * 3 * E_, (size_t)Q_ * 3 * E_, (size_t)C_ * Q_,
            p_cw, C_, p_qw, Q_, nullptr,
            p_sim, nullptr, 0, 0);
    }
    softmax_q_kernel<<<B_ * C_, Q_>>>();

    // c2q = probs @ question   (tensor)
    {
        dim3 grid(E_ / 128, C_ / 128, B_);
        mma_gemm_kernel<<<grid, 256, SMEM_TOTAL>>>(
            p_ps, p_qTs, E_, 3 * Q_,
            (size_t)C_ * 3 * Q_, (size_t)E_ * 3 * Q_, (size_t)C_ * E_,
            nullptr, 0, nullptr, 0, nullptr,
            p_c2q, nullptr, 0, 0);
    }

    // q2c
    q2c_w_kernel<<<B_, 256>>>();
    {
        dim3 grid(E_ / 256, B_);
        q2c_sum_kernel<<<grid, 256>>>(context);
    }

    build_attended_split_kernel<<<(B_ * C_ * E_ + 255) / 256, 256>>>(context);

    // MLP1: [8192 x 6144] @ W1'^T -> split bf16 A2'
    {
        dim3 grid(H_ / 128, (B_ * C_) / 128, 1);
        mma_gemm_kernel<<<grid, 256, SMEM_TOTAL>>>(
            p_A1, p_B1, H_, 3 * FE, 0, 0, 0,
            nullptr, 0, b1, 0, mask,
            nullptr, p_A2, H_, 0);
    }
    // MLP2: [8192 x 3072] @ W2'^T -> fp32 out with relu
    {
        dim3 grid(FE / 128, (B_ * C_) / 128, 1);
        mma_gemm_kernel<<<grid, 256, SMEM_TOTAL>>>(
            p_A2, p_B2, FE, 3 * H_, 0, 0, 0,
            nullptr, 0, b2, 0, mask,
            out, nullptr, 0, 1);
    }
}

// round 9
// speedup vs baseline: 3.5172x; 1.4088x over previous
#include <cuda_runtime.h>
#include <cuda_fp16.h>
#include <cstdint>
#include <cstddef>

#define B_ 8
#define C_ 1024
#define Q_ 128
#define E_ 512
#define H_ 1024
#define FE (4 * E_)   // 2048
#define WSCALE 256.0f
#define INV_WSCALE (1.0f / 256.0f)

// ---------------- helpers ----------------
__device__ __forceinline__ uint32_t smem_u32(const void* p) {
    uint32_t a;
    asm("{ .reg .u64 t; cvta.to.shared.u64 t, %1; cvt.u32.u64 %0, t; }" : "=r"(a) : "l"(p));
    return a;
}
#define CP_ASYNC16(dst, src) \
    asm volatile("cp.async.cg.shared.global [%0], [%1], 16;" :: "r"(dst), "l"(src) : "memory")
#define CP_COMMIT() asm volatile("cp.async.commit_group;" ::: "memory")

__device__ __forceinline__ void split_fp16(float v, __half& hi, __half& lo) {
    hi = __float2half(v);
    lo = __float2half(v - __half2float(hi));
}

// ---------------- scratch ----------------
__device__ float g_qw[B_ * Q_];
__device__ float g_cw[B_ * C_];
__device__ float g_sim[B_ * C_ * Q_];
__device__ float g_rowmax[B_ * C_];
__device__ float g_cwgt[B_ * C_];
__device__ float g_c2q[B_ * C_ * E_];
__device__ float g_q2c[B_ * E_];
// sim uses 3-term split (softmax sensitivity); everything else 2-term fp16
__device__ __half g_ctxS[(size_t)B_ * C_ * 3 * E_];   // sim A  [hi|lo|hi]
__device__ __half g_qmS[(size_t)B_ * Q_ * 3 * E_];    // sim B  [hi|hi|lo]
__device__ __half g_ps[(size_t)B_ * C_ * 2 * Q_];     // c2q A  [hi|lo]
__device__ __half g_qTs[(size_t)B_ * E_ * 2 * Q_];    // c2q B  [hi|hi]
__device__ __half g_A1[(size_t)B_ * C_ * 2 * FE];     // MLP1 A [hi|lo]
__device__ __half g_B1[(size_t)H_ * 2 * FE];          // MLP1 B [hi|hi] (scaled)
__device__ __half g_A2[(size_t)B_ * C_ * 2 * H_];     // MLP2 A [hi|lo]
__device__ __half g_B2[(size_t)FE * 2 * H_];          // MLP2 B [hi|hi] (scaled)

// ---------------- fused preprocess: dot + split ----------------
__global__ void ctx_pre_kernel(const float* __restrict__ context,
                               const float* __restrict__ w_context) {
    int row = blockIdx.x;                    // b*C + c
    const float4* x4 = (const float4*)(context + (size_t)row * E_);
    const float4* w4 = (const float4*)w_context;
    __half* o = g_ctxS + (size_t)row * (3 * E_);
    float s = 0.f;
    for (int i = threadIdx.x; i < E_ / 4; i += 128) {
        float4 xv = x4[i], wv = w4[i];
        s += xv.x * wv.x + xv.y * wv.y + xv.z * wv.z + xv.w * wv.w;
        float v[4] = { xv.x, xv.y, xv.z, xv.w };
        #pragma unroll
        for (int j = 0; j < 4; j++) {
            __half hi, lo; split_fp16(v[j], hi, lo);
            int e = i * 4 + j;
            o[e] = hi; o[E_ + e] = lo; o[2 * E_ + e] = hi;
        }
    }
    __shared__ float red[4];
    #pragma unroll
    for (int off = 16; off > 0; off >>= 1) s += __shfl_down_sync(0xffffffffu, s, off);
    if ((threadIdx.x & 31) == 0) red[threadIdx.x >> 5] = s;
    __syncthreads();
    if (threadIdx.x == 0) g_cw[row] = red[0] + red[1] + red[2] + red[3];
}

__global__ void q_pre_kernel(const float* __restrict__ question,
                             const float* __restrict__ w_question,
                             const float* __restrict__ w_multiple) {
    int row = blockIdx.x;                    // b*Q + q
    const float4* x4 = (const float4*)(question + (size_t)row * E_);
    const float4* wq4 = (const float4*)w_question;
    const float4* wm4 = (const float4*)w_multiple;
    __half* o = g_qmS + (size_t)row * (3 * E_);
    float s = 0.f;
    for (int i = threadIdx.x; i < E_ / 4; i += 128) {
        float4 xv = x4[i], wq = wq4[i], wm = wm4[i];
        s += xv.x * wq.x + xv.y * wq.y + xv.z * wq.z + xv.w * wq.w;
        float v[4] = { xv.x * wm.x, xv.y * wm.y, xv.z * wm.z, xv.w * wm.w };
        #pragma unroll
        for (int j = 0; j < 4; j++) {
            __half hi, lo; split_fp16(v[j], hi, lo);
            int e = i * 4 + j;
            o[e] = hi; o[E_ + e] = hi; o[2 * E_ + e] = lo;
        }
    }
    __shared__ float red[4];
    #pragma unroll
    for (int off = 16; off > 0; off >>= 1) s += __shfl_down_sync(0xffffffffu, s, off);
    if ((threadIdx.x & 31) == 0) red[threadIdx.x >> 5] = s;
    __syncthreads();
    if (threadIdx.x == 0) g_qw[row] = red[0] + red[1] + red[2] + red[3];
}

// question^T for c2q B: [hi|hi] width 2Q
__global__ void qT_split_kernel(const float* __restrict__ question) {
    __shared__ float tile[32][33];
    int b = blockIdx.z;
    int e0 = blockIdx.x * 32, q0 = blockIdx.y * 32;
    int tx = threadIdx.x, ty = threadIdx.y;      // (32, 8)
    #pragma unroll
    for (int j = 0; j < 4; j++) {
        int qi = ty * 4 + j;
        tile[qi][tx] = question[((size_t)b * Q_ + q0 + qi) * E_ + e0 + tx];
    }
    __syncthreads();
    #pragma unroll
    for (int j = 0; j < 4; j++) {
        int ei = ty * 4 + j;
        __half hi = __float2half(tile[tx][ei]);
        __half* r = g_qTs + ((size_t)b * E_ + e0 + ei) * (2 * Q_);
        r[q0 + tx] = hi; r[Q_ + q0 + tx] = hi;
    }
}

// W (fp32, [K x N]) -> B' (fp16, [N x 2K]) = [hi|hi], scaled by WSCALE
__global__ void split_w_kernel(const float* __restrict__ W, __half* __restrict__ Bt,
                               int K, int N) {
    int idx = blockIdx.x * blockDim.x + threadIdx.x;
    if (idx >= K * N) return;
    int k = idx % K;
    int n = idx / K;
    __half hi = __float2half(W[(size_t)k * N + n] * WSCALE);
    __half* row = Bt + (size_t)n * (2 * K);
    row[k] = hi; row[K + k] = hi;
}

// ---------------- softmax over q: probs -> [hi|lo], keep rowmax ----------------
__global__ void softmax_q_kernel() {
    int row = blockIdx.x;                    // b*C + c
    const float* s = g_sim + (size_t)row * Q_;
    int t = threadIdx.x;                     // 128
    float v = s[t];
    __shared__ float sh[Q_];
    sh[t] = v; __syncthreads();
    #pragma unroll
    for (int o = 64; o > 0; o >>= 1) { if (t < o) sh[t] = fmaxf(sh[t], sh[t + o]); __syncthreads(); }
    float m = sh[0]; __syncthreads();
    if (t == 0) g_rowmax[row] = m;
    float e = expf(v - m);
    sh[t] = e; __syncthreads();
    #pragma unroll
    for (int o = 64; o > 0; o >>= 1) { if (t < o) sh[t] += sh[t + o]; __syncthreads(); }
    float p = e / sh[0];
    __half hi, lo; split_fp16(p, hi, lo);
    __half* r = g_ps + (size_t)row * (2 * Q_);
    r[t] = hi; r[Q_ + t] = lo;
}

// ---------------- q2c ----------------
__global__ void q2c_w_kernel() {
    int b = blockIdx.x;
    int t = threadIdx.x;                     // 256
    __shared__ float red[256];
    const float* rm = g_rowmax + b * C_;
    float mx = -1e30f;
    for (int c = t; c < C_; c += 256) mx = fmaxf(mx, rm[c]);
    red[t] = mx; __syncthreads();
    #pragma unroll
    for (int o = 128; o > 0; o >>= 1) { if (t < o) red[t] = fmaxf(red[t], red[t + o]); __syncthreads(); }
    mx = red[0]; __syncthreads();
    float sum = 0.f;
    for (int c = t; c < C_; c += 256) { float e = expf(rm[c] - mx); g_cwgt[b * C_ + c] = e; sum += e; }
    red[t] = sum; __syncthreads();
    #pragma unroll
    for (int o = 128; o > 0; o >>= 1) { if (t < o) red[t] += red[t + o]; __syncthreads(); }
    float inv = 1.f / red[0];
    for (int c = t; c < C_; c += 256) g_cwgt[b * C_ + c] *= inv;
}

__global__ void q2c_sum_kernel(const float* __restrict__ context) {
    int b = blockIdx.y;
    int e = blockIdx.x * 256 + threadIdx.x;  // E=512 -> grid.x=2
    __shared__ float w[C_];
    for (int c = threadIdx.x; c < C_; c += 256) w[c] = g_cwgt[b * C_ + c];
    __syncthreads();
    const float* ctx = context + (size_t)b * C_ * E_ + e;
    float acc = 0.f;
    #pragma unroll 8
    for (int c = 0; c < C_; c++) acc += w[c] * ctx[(size_t)c * E_];
    g_q2c[b * E_ + e] = acc;
}

// ---------------- attended -> A1' = [hi|lo], width 2*FE ----------------
__global__ void build_attended_split_kernel(const float* __restrict__ context) {
    size_t idx = (size_t)blockIdx.x * blockDim.x + threadIdx.x;
    if (idx >= (size_t)B_ * C_ * E_) return;
    int e = (int)(idx % E_);
    size_t bc = idx / E_;
    int b = (int)(bc / C_);
    float ctx = context[idx];
    float cq = g_c2q[idx];
    float qc = g_q2c[b * E_ + e];
    float vals[4] = { ctx, cq, ctx * cq, ctx * qc };
    __half* row = g_A1 + bc * (size_t)(2 * FE);
    #pragma unroll
    for (int j = 0; j < 4; j++) {
        int col = j * E_ + e;
        __half hi, lo; split_fp16(vals[j], hi, lo);
        row[col] = hi;
        row[FE + col] = lo;
    }
}

// ---------------- generic mma.sync fp16 GEMM ----------------
// C[bz] = A'[bz](M x Kp) @ B'[bz](N x Kp)^T
// epilogue: v = (acc*invScale + rowAdd[bz*sRow+m] + colAdd[bz*sCol+n]) * rowMul[m]; relu optional
// outSplit!=null: write fp16 [hi|lo] rows of width 2*splitK ; else fp32 at outF
#define LDA 40                            // 32 + 8 pad; conflict-free ldmatrix
#define STAGE_BYTES (2 * 128 * LDA * 2)   // A + B per stage = 20480
#define SMEM_TOTAL (3 * STAGE_BYTES)      // 61440

__global__ __launch_bounds__(256, 2) void mma_gemm_kernel(
    const __half* __restrict__ A, const __half* __restrict__ Bt,
    int N, int Kp,
    size_t sA, size_t sB, size_t sO,
    const float* __restrict__ rowAdd, int sRow,
    const float* __restrict__ colAdd, int sCol,
    const float* __restrict__ rowMul, float invScale,
    float* __restrict__ outF, __half* __restrict__ outSplit, int splitK, int relu) {
    extern __shared__ char smem[];
    uint32_t sb = smem_u32(smem);
    int tid = threadIdx.x;
    int wid = tid >> 5, lane = tid & 31;
    int warpM = wid >> 2, warpN = wid & 3;            // 2 x 4 warps -> 64 x 32 per warp
    int bz = blockIdx.z;
    int mrow0 = blockIdx.y * 128;
    int ncol0 = blockIdx.x * 128;
    const __half* Ag = A + bz * sA + (size_t)mrow0 * Kp;
    const __half* Bg = Bt + bz * sB + (size_t)ncol0 * Kp;

    float acc[4][4][4];
    #pragma unroll
    for (int mi = 0; mi < 4; mi++)
        #pragma unroll
        for (int nj = 0; nj < 4; nj++)
            #pragma unroll
            for (int r = 0; r < 4; r++) acc[mi][nj][r] = 0.f;

    auto load_stage = [&](int ch, int st) {
        int k0 = ch * 32;
        uint32_t abase = sb + st * STAGE_BYTES;
        uint32_t bbase = abase + 128 * LDA * 2;
        #pragma unroll
        for (int j = 0; j < 2; j++) {
            int idx = tid + j * 256;                 // 0..511
            int r = idx >> 2, s = idx & 3;
            CP_ASYNC16(abase + (uint32_t)(r * LDA + s * 8) * 2, Ag + (size_t)r * Kp + k0 + s * 8);
        }
        #pragma unroll
        for (int j = 0; j < 2; j++) {
            int idx = tid + j * 256;
            int r = idx >> 2, s = idx & 3;
            CP_ASYNC16(bbase + (uint32_t)(r * LDA + s * 8) * 2, Bg + (size_t)r * Kp + k0 + s * 8);
        }
        CP_COMMIT();
    };

    int nCh = Kp >> 5;
    load_stage(0, 0);
    if (nCh > 1) load_stage(1, 1);
    int st = 0;
    for (int i = 0; i < nCh; i++) {
        if (i + 1 < nCh) {
            asm volatile("cp.async.wait_group 1;" ::: "memory");
        } else {
            asm volatile("cp.async.wait_group 0;" ::: "memory");
        }
        __syncthreads();
        if (i + 2 < nCh) {
            int nst = st + 2; if (nst >= 3) nst -= 3;
            load_stage(i + 2, nst);
        }
        uint32_t abase = sb + st * STAGE_BYTES;
        uint32_t bbase = abase + 128 * LDA * 2;
        #pragma unroll
        for (int ks = 0; ks < 2; ks++) {
            uint32_t afrag[4][4];
            uint32_t bfrag[4][2];
            int arow = warpM * 64 + (lane & 15);
            int acol = ks * 16 + (lane >> 4) * 8;
            #pragma unroll
            for (int mi = 0; mi < 4; mi++) {
                uint32_t addr = abase + (uint32_t)((arow + mi * 16) * LDA + acol) * 2;
                asm volatile("ldmatrix.sync.aligned.m8n8.x4.shared.b16 {%0,%1,%2,%3}, [%4];"
                    : "=r"(afrag[mi][0]), "=r"(afrag[mi][1]), "=r"(afrag[mi][2]), "=r"(afrag[mi][3])
                    : "r"(addr));
            }
            int brow = warpN * 32 + (lane & 7) + ((lane >> 4) << 3);
            int bcol = ks * 16 + ((lane >> 3) & 1) * 8;
            #pragma unroll
            for (int p = 0; p < 2; p++) {
                uint32_t addr = bbase + (uint32_t)((brow + p * 16) * LDA + bcol) * 2;
                asm volatile("ldmatrix.sync.aligned.m8n8.x4.shared.b16 {%0,%1,%2,%3}, [%4];"
                    : "=r"(bfrag[2 * p][0]), "=r"(bfrag[2 * p][1]),
                      "=r"(bfrag[2 * p + 1][0]), "=r"(bfrag[2 * p + 1][1])
                    : "r"(addr));
            }
            #pragma unroll
            for (int mi = 0; mi < 4; mi++)
                #pragma unroll
                for (int nj = 0; nj < 4; nj++)
                    asm volatile(
                        "mma.sync.aligned.m16n8k16.row.col.f32.f16.f16.f32 "
                        "{%0,%1,%2,%3}, {%4,%5,%6,%7}, {%8,%9}, {%0,%1,%2,%3};"
                        : "+f"(acc[mi][nj][0]), "+f"(acc[mi][nj][1]),
                          "+f"(acc[mi][nj][2]), "+f"(acc[mi][nj][3])
                        : "r"(afrag[mi][0]), "r"(afrag[mi][1]), "r"(afrag[mi][2]), "r"(afrag[mi][3]),
                          "r"(bfrag[nj][0]), "r"(bfrag[nj][1]));
        }
        __syncthreads();
        if (++st == 3) st = 0;
    }

    // epilogue straight from register fragments
    #pragma unroll
    for (int mi = 0; mi < 4; mi++) {
        #pragma unroll
        for (int half = 0; half < 2; half++) {
            int m = mrow0 + warpM * 64 + mi * 16 + half * 8 + (lane >> 2);
            float ra = rowAdd ? rowAdd[bz * sRow + m] : 0.f;
            float rmul = rowMul ? rowMul[m] : 1.f;
            #pragma unroll
            for (int nj = 0; nj < 4; nj++) {
                int n = ncol0 + warpN * 32 + nj * 8 + (lane & 3) * 2;
                float ca0 = colAdd ? colAdd[bz * sCol + n] : 0.f;
                float ca1 = colAdd ? colAdd[bz * sCol + n + 1] : 0.f;
                float v0 = (acc[mi][nj][half * 2 + 0] * invScale + ra + ca0) * rmul;
                float v1 = (acc[mi][nj][half * 2 + 1] * invScale + ra + ca1) * rmul;
                if (outSplit) {
                    __half* row = outSplit + (size_t)m * (2 * splitK);
                    __half h0, l0, h1, l1;
                    split_fp16(v0, h0, l0);
                    split_fp16(v1, h1, l1);
                    row[n] = h0;           row[n + 1] = h1;
                    row[splitK + n] = l0;  row[splitK + n + 1] = l1;
                } else {
                    if (relu) { v0 = fmaxf(v0, 0.f); v1 = fmaxf(v1, 0.f); }
                    float* o = outF + bz * sO;
                    o[(size_t)m * N + n] = v0;
                    o[(size_t)m * N + n + 1] = v1;
                }
            }
        }
    }
}

// ---------------- launch ----------------
extern "C" void kernel_launch(void* const* d_in, const int* in_sizes, int n_in,
                              void* d_out, int out_size) {
    const float* context    = (const float*)d_in[0];
    const float* question   = (const float*)d_in[1];
    const float* mask       = (const float*)d_in[2];
    const float* w_question = (const float*)d_in[3];
    const float* w_context  = (const float*)d_in[4];
    const float* w_multiple = (const float*)d_in[5];
    const float* W1         = (const float*)d_in[6];
    const float* b1         = (const float*)d_in[7];
    const float* W2         = (const float*)d_in[8];
    const float* b2         = (const float*)d_in[9];
    float* out = (float*)d_out;

    float *p_sim, *p_c2q, *p_qw, *p_cw;
    __half *p_ctxS, *p_qmS, *p_ps, *p_qTs, *p_A1, *p_B1, *p_A2, *p_B2;
    cudaGetSymbolAddress((void**)&p_sim, g_sim);
    cudaGetSymbolAddress((void**)&p_c2q, g_c2q);
    cudaGetSymbolAddress((void**)&p_qw, g_qw);
    cudaGetSymbolAddress((void**)&p_cw, g_cw);
    cudaGetSymbolAddress((void**)&p_ctxS, g_ctxS);
    cudaGetSymbolAddress((void**)&p_qmS, g_qmS);
    cudaGetSymbolAddress((void**)&p_ps, g_ps);
    cudaGetSymbolAddress((void**)&p_qTs, g_qTs);
    cudaGetSymbolAddress((void**)&p_A1, g_A1);
    cudaGetSymbolAddress((void**)&p_B1, g_B1);
    cudaGetSymbolAddress((void**)&p_A2, g_A2);
    cudaGetSymbolAddress((void**)&p_B2, g_B2);

    cudaFuncSetAttribute(mma_gemm_kernel, cudaFuncAttributeMaxDynamicSharedMemorySize,
                         SMEM_TOTAL);

    // weight splits (scaled fp16 [hi|hi])
    split_w_kernel<<<(FE * H_ + 255) / 256, 256>>>(W1, p_B1, FE, H_);
    split_w_kernel<<<(H_ * FE + 255) / 256, 256>>>(W2, p_B2, H_, FE);

    // preprocess: dots + splits
    ctx_pre_kernel<<<B_ * C_, 128>>>(context, w_context);
    q_pre_kernel<<<B_ * Q_, 128>>>(question, w_question, w_multiple);
    {
        dim3 grid(E_ / 32, Q_ / 32, B_);
        qT_split_kernel<<<grid, dim3(32, 8)>>>(question);
    }

    // sim = context @ (question*w_mult)^T + cw[row] + qw[col]   (3-term fp16)
    {
        dim3 grid(Q_ / 128, C_ / 128, B_);
        mma_gemm_kernel<<<grid, 256, SMEM_TOTAL>>>(
            p_ctxS, p_qmS, Q_, 3 * E_,
            (size_t)C_ * 3 * E_, (size_t)Q_ * 3 * E_, (size_t)C_ * Q_,
            p_cw, C_, p_qw, Q_, nullptr, 1.0f,
            p_sim, nullptr, 0, 0);
    }
    softmax_q_kernel<<<B_ * C_, Q_>>>();

    // c2q = probs @ question   (2-term fp16)
    {
        dim3 grid(E_ / 128, C_ / 128, B_);
        mma_gemm_kernel<<<grid, 256, SMEM_TOTAL>>>(
            p_ps, p_qTs, E_, 2 * Q_,
            (size_t)C_ * 2 * Q_, (size_t)E_ * 2 * Q_, (size_t)C_ * E_,
            nullptr, 0, nullptr, 0, nullptr, 1.0f,
            p_c2q, nullptr, 0, 0);
    }

    // q2c
    q2c_w_kernel<<<B_, 256>>>();
    {
        dim3 grid(E_ / 256, B_);
        q2c_sum_kernel<<<grid, 256>>>(context);
    }

    build_attended_split_kernel<<<(B_ * C_ * E_ + 255) / 256, 256>>>(context);

    // MLP1: [8192 x 4096] @ W1'^T (scaled) -> split fp16 A2'
    {
        dim3 grid(H_ / 128, (B_ * C_) / 128, 1);
        mma_gemm_kernel<<<grid, 256, SMEM_TOTAL>>>(
            p_A1, p_B1, H_, 2 * FE, 0, 0, 0,
            nullptr, 0, b1, 0, mask, INV_WSCALE,
            nullptr, p_A2, H_, 0);
    }
    // MLP2: [8192 x 2048] @ W2'^T (scaled) -> fp32 out with relu
    {
        dim3 grid(FE / 128, (B_ * C_) / 128, 1);
        mma_gemm_kernel<<<grid, 256, SMEM_TOTAL>>>(
            p_A2, p_B2, FE, 2 * H_, 0, 0, 0,
            nullptr, 0, b2, 0, mask, INV_WSCALE,
            out, nullptr, 0, 1);
    }
}